// round 9
// baseline (speedup 1.0000x reference)
#include <cuda_runtime.h>
#include <cuda_bf16.h>
#include <math.h>
#include <stdint.h>

#define NATOMS 20000
#define NEDGES 200000
#define CDIM 64
#define KDIM 20
#define RCUT 5.0f
#define NORMF 10.0f
#define EPSF 1e-12f
#define PI_F 3.14159265358979f
#define NC (NATOMS * CDIM)

// ---- dynamic smem layout (byte offsets from 1024-aligned base) ----
// W: 3 ways x {hi,lo} x (64 rows(o) x 128B(cc)) SW128          = 49152
// A: {hi,lo} x (208 rows x 128B(cc)) SW128                     = 53248
// Y: 208 rows x 65 floats                                      = 54080
#define OFF_W    0
#define OFF_A    49152
#define A_HALF   26624
#define OFF_Y    102400
#define OFF_CTRL 156480     // b0s[64] @ +0, aws[192] @ +256
#define DYN_SZ   (OFF_CTRL + 1024 + 1024)

__device__ float g_scr[(size_t)13 * NC];
__device__ int g_active[NEDGES];
__device__ int g_flag[NATOMS];
__device__ int g_touched[NATOMS];
__device__ int g_count;
__device__ int g_ntouched;

__global__ void k_reset() {
    int idx = blockIdx.x * blockDim.x + threadIdx.x;
    if (idx < NATOMS) g_flag[idx] = 0;
    if (idx == 0) { g_count = 0; g_ntouched = 0; }
}

__global__ void k_compact(const int* __restrict__ eidx, const float* __restrict__ coord) {
    int e = blockIdx.x * blockDim.x + threadIdx.x;
    if (e >= NEDGES) return;
    int i = eidx[e];
    int j = eidx[NEDGES + e];
    float dx = coord[3 * j + 0] - coord[3 * i + 0];
    float dy = coord[3 * j + 1] - coord[3 * i + 1];
    float dz = coord[3 * j + 2] - coord[3 * i + 2];
    float d2 = dx * dx + dy * dy + dz * dz + EPSF;
    if (d2 < RCUT * RCUT) {     // fc == 0 exactly (fp32) beyond cutoff
        int p = atomicAdd(&g_count, 1);
        g_active[p] = e;
        if (atomicOr(&g_flag[i], 1) == 0) {
            int q = atomicAdd(&g_ntouched, 1);
            g_touched[q] = i;
        }
    }
}

__global__ void k_zero_touched() {
    const int nt = g_ntouched;
    for (int t = blockIdx.x; t < nt; t += gridDim.x) {
        size_t b = (size_t)g_touched[t] * CDIM + threadIdx.x;   // 64 threads
#pragma unroll
        for (int s = 0; s < 13; s++) g_scr[(size_t)s * NC + b] = 0.f;
    }
}

__global__ void k_edge(const int* __restrict__ eidx, const float* __restrict__ coord,
                       const float* __restrict__ t0, const float* __restrict__ t1,
                       const float* __restrict__ t2, const float* __restrict__ rbf_w) {
    __shared__ float rbf_sh[4][KDIM];
    const int tid = threadIdx.x;
    const int c = tid & 63;
    const int es = tid >> 6;
    const int count = g_count;

    for (int base = blockIdx.x * 4; base < count; base += gridDim.x * 4) {
        int ae = base + es;
        bool act = ae < count;
        int i = 0, j = 0;
        float ux = 0.f, uy = 0.f, uz = 0.f;
        if (act) {
            int e = g_active[ae];
            i = eidx[e];
            j = eidx[NEDGES + e];
            float dx = coord[3 * j + 0] - coord[3 * i + 0];
            float dy = coord[3 * j + 1] - coord[3 * i + 1];
            float dz = coord[3 * j + 2] - coord[3 * i + 2];
            float d2 = dx * dx + dy * dy + dz * dz + EPSF;
            float d = sqrtf(d2);
            float inv = 1.0f / d;
            ux = dx * inv; uy = dy * inv; uz = dz * inv;
            if (c < KDIM) {
                float x = fminf(d * (1.0f / RCUT), 1.0f);
                float fc = 0.5f * (cosf(PI_F * x) + 1.0f);
                float pref = sqrtf(2.0f / RCUT);
                rbf_sh[es][c] = pref * sinf((float)(c + 1) * PI_F * d * (1.0f / RCUT)) * inv * fc;
            }
        }
        __syncthreads();
        if (act) {
            float rbf[KDIM];
#pragma unroll
            for (int k = 0; k < KDIM; k++) rbf[k] = rbf_sh[es][k];

            float fn[11];
            for (int m = 0; m < 11; m++) {
                const float* w = rbf_w + (size_t)m * KDIM * CDIM + c;
                float acc = 0.f;
#pragma unroll
                for (int k = 0; k < KDIM; k++) acc += rbf[k] * __ldg(w + k * CDIM);
                fn[m] = acc;
            }

            size_t bj = (size_t)j * CDIM + c;
            float s0 = __ldg(t0 + bj);
            float va[3];
            va[0] = __ldg(t1 + bj * 3 + 0);
            va[1] = __ldg(t1 + bj * 3 + 1);
            va[2] = __ldg(t1 + bj * 3 + 2);
            float M[9];
#pragma unroll
            for (int m9 = 0; m9 < 9; m9++) M[m9] = __ldg(t2 + bj * 9 + m9);

            float u[3] = {ux, uy, uz};
            float d1 = va[0] * ux + va[1] * uy + va[2] * uz;
            float w3[3];
#pragma unroll
            for (int a = 0; a < 3; a++)
                w3[a] = M[a * 3 + 0] * ux + M[a * 3 + 1] * uy + M[a * 3 + 2] * uz;
            float q2 = w3[0] * ux + w3[1] * uy + w3[2] * uz;

            const float sc = 1.0f / NORMF;
            float o0 = (fn[0] * s0 + fn[4] * d1 + fn[9] * q2) * sc;
            float c1 = fn[1] * s0 + fn[6] * d1;
            float o1[3];
#pragma unroll
            for (int p = 0; p < 3; p++)
                o1[p] = (c1 * u[p] + fn[3] * va[p] + fn[8] * w3[p]) * sc;
            float o2[9];
#pragma unroll
            for (int a = 0; a < 3; a++) {
                float ga = fn[2] * s0 * u[a] + fn[5] * va[a] + fn[10] * w3[a];
#pragma unroll
                for (int b = 0; b < 3; b++)
                    o2[a * 3 + b] = (ga * u[b] + fn[7] * M[a * 3 + b]) * sc;
            }

            size_t bi = (size_t)i * CDIM + c;
            atomicAdd(&g_scr[bi], o0);
#pragma unroll
            for (int p = 0; p < 3; p++) atomicAdd(&g_scr[(size_t)(1 + p) * NC + bi], o1[p]);
#pragma unroll
            for (int m9 = 0; m9 < 9; m9++) atomicAdd(&g_scr[(size_t)(4 + m9) * NC + bi], o2[m9]);
        }
        __syncthreads();
    }
}

// ---- warp-mma helpers (base ISA, compiles for sm_103 without 'a') ----
__device__ __forceinline__ uint32_t smem_u32(const void* p) {
    uint32_t a;
    asm("{ .reg .u64 t; cvta.to.shared.u64 t, %1; cvt.u32.u64 %0, t; }" : "=r"(a) : "l"(p));
    return a;
}
__device__ __forceinline__ uint32_t sw128(uint32_t o) { return o ^ ((o >> 3) & 0x70); }
__device__ __forceinline__ void ldsm4(uint32_t d[4], uint32_t addr) {
    asm volatile("ldmatrix.sync.aligned.m8n8.x4.shared.b16 {%0,%1,%2,%3}, [%4];"
                 : "=r"(d[0]), "=r"(d[1]), "=r"(d[2]), "=r"(d[3]) : "r"(addr));
}
__device__ __forceinline__ void ldsm2(uint32_t d[2], uint32_t addr) {
    asm volatile("ldmatrix.sync.aligned.m8n8.x2.shared.b16 {%0,%1}, [%2];"
                 : "=r"(d[0]), "=r"(d[1]) : "r"(addr));
}
__device__ __forceinline__ void mma_bf16(float c[4], const uint32_t a[4],
                                         uint32_t b0, uint32_t b1) {
    asm volatile("mma.sync.aligned.m16n8k16.row.col.f32.bf16.bf16.f32 "
                 "{%0,%1,%2,%3}, {%4,%5,%6,%7}, {%8,%9}, {%0,%1,%2,%3};"
                 : "+f"(c[0]), "+f"(c[1]), "+f"(c[2]), "+f"(c[3])
                 : "r"(a[0]), "r"(a[1]), "r"(a[2]), "r"(a[3]), "r"(b0), "r"(b1));
}
__device__ __forceinline__ float sigf(float x) { return 1.0f / (1.0f + __expf(-x)); }

// Persistent split-bf16 mma.sync self-interaction.
// Tile = 16 atoms -> A rows: way0 [0,16), way1 [16,64), way2 [64,208). 13 chunks of 16.
// Warp w (<13) computes chunk w: D[16x64] = Ah*Wh + Ah*Wl + Al*Wh (fp32 acc).
__global__ void __launch_bounds__(512, 1)
k_si_mma(const float* __restrict__ t0, const float* __restrict__ t1,
         const float* __restrict__ t2,
         const float* __restrict__ w0, const float* __restrict__ b0,
         const float* __restrict__ w1, const float* __restrict__ w2,
         const float* __restrict__ actw, float* __restrict__ out) {
    extern __shared__ char dsm[];
    uint32_t sb_raw = smem_u32(dsm);
    uint32_t base = (sb_raw + 1023u) & ~1023u;
    char* B = dsm + (base - sb_raw);
    float* Y = (float*)(B + OFF_Y);
    float* b0s = (float*)(B + OFF_CTRL);
    float* aws = (float*)(B + OFF_CTRL + 256);

    const int tid = threadIdx.x;
    const int w = tid >> 5, lane = tid & 31;

    // ---- load W^T split hi/lo, SW128 (row = out channel o, col = cc) ----
    for (int idx = tid; idx < 3 * 64 * 64; idx += 512) {
        int way = idx >> 12, rem = idx & 4095;
        int o = rem >> 6, cc = rem & 63;
        const float* wsrc = (way == 0) ? w0 : ((way == 1) ? w1 : w2);
        float f = wsrc[cc * 64 + o];
        __nv_bfloat16 h = __float2bfloat16(f);
        __nv_bfloat16 l = __float2bfloat16(f - __bfloat162float(h));
        uint32_t off = sw128((uint32_t)(o * 128 + cc * 2));
        *(__nv_bfloat16*)(B + OFF_W + way * 16384 + off) = h;
        *(__nv_bfloat16*)(B + OFF_W + way * 16384 + 8192 + off) = l;
    }
    if (tid < 64) {
        b0s[tid] = b0[tid];
        aws[tid] = actw[tid];
        aws[64 + tid] = actw[64 + tid];
        aws[128 + tid] = actw[128 + tid];
    }
    __syncthreads();

    float* out1 = out + (size_t)NATOMS * CDIM;
    float* out2 = out + (size_t)NATOMS * CDIM * 4;

    for (int tile = blockIdx.x; tile < NATOMS / 16; tile += gridDim.x) {
        const int nbase = tile * 16;

        // ---- stage: agg fp32 = t + scr(touched), split to Ahi/Alo bf16 ----
        {
            int sc = tid & 63;
#pragma unroll
            for (int pass = 0; pass < 2; pass++) {
                int aa = (tid >> 6) + pass * 8;
                int n_a = nbase + aa;
                size_t gb = (size_t)n_a * CDIM + sc;
                float v[13];
                v[0] = t0[gb];
#pragma unroll
                for (int p = 0; p < 3; p++) v[1 + p] = t1[gb * 3 + p];
#pragma unroll
                for (int m = 0; m < 9; m++) v[4 + m] = t2[gb * 9 + m];
                if (g_flag[n_a]) {
#pragma unroll
                    for (int s = 0; s < 13; s++) v[s] += g_scr[(size_t)s * NC + gb];
                }
                int rows[13];
                rows[0] = aa;
#pragma unroll
                for (int p = 0; p < 3; p++) rows[1 + p] = 16 + aa * 3 + p;
#pragma unroll
                for (int m = 0; m < 9; m++) rows[4 + m] = 64 + aa * 9 + m;
#pragma unroll
                for (int s = 0; s < 13; s++) {
                    __nv_bfloat16 h = __float2bfloat16(v[s]);
                    __nv_bfloat16 l = __float2bfloat16(v[s] - __bfloat162float(h));
                    uint32_t off = sw128((uint32_t)(rows[s] * 128 + sc * 2));
                    *(__nv_bfloat16*)(B + OFF_A + off) = h;
                    *(__nv_bfloat16*)(B + OFF_A + A_HALF + off) = l;
                }
            }
        }
        __syncthreads();

        // ---- mma: warp w computes chunk w ----
        if (w < 13) {
            int way = (w == 0) ? 0 : ((w < 4) ? 1 : 2);
            uint32_t WhB = base + OFF_W + way * 16384;
            uint32_t WlB = WhB + 8192;
            uint32_t AhB = base + OFF_A, AlB = AhB + A_HALF;
            int rb = w * 16;
            int g = lane >> 3, lr = lane & 7;
            int arow = rb + ((g & 1) << 3) + lr;     // m16n8k16 A frag row for this lane group
            int acx = (g >> 1) << 4;                 // +16B for k 8..15 halves
            uint32_t ah[4][4], al[4][4];
#pragma unroll
            for (int kc = 0; kc < 4; kc++) {
                uint32_t off = sw128((uint32_t)(arow * 128 + kc * 32 + acx));
                ldsm4(ah[kc], AhB + off);
                ldsm4(al[kc], AlB + off);
            }
            float c[8][4];
#pragma unroll
            for (int nb = 0; nb < 8; nb++)
#pragma unroll
                for (int q = 0; q < 4; q++) c[nb][q] = 0.f;

            int bl = lane & 15;
            int brow_l = bl & 7, bhalf = bl >> 3;    // lanes 0-7: k 0-7 box, 8-15: k 8-15 box
#pragma unroll
            for (int nb = 0; nb < 8; nb++) {
#pragma unroll
                for (int kc = 0; kc < 4; kc++) {
                    uint32_t boff = sw128((uint32_t)((nb * 8 + brow_l) * 128 + kc * 32 + bhalf * 16));
                    uint32_t bh[2], blo[2];
                    ldsm2(bh, WhB + boff);
                    ldsm2(blo, WlB + boff);
                    mma_bf16(c[nb], ah[kc], bh[0], bh[1]);
                    mma_bf16(c[nb], ah[kc], blo[0], blo[1]);
                    mma_bf16(c[nb], al[kc], bh[0], bh[1]);
                }
            }
            // D frag -> Y
            int dr = rb + (lane >> 2), dn = (lane & 3) * 2;
#pragma unroll
            for (int nb = 0; nb < 8; nb++) {
                Y[dr * 65 + nb * 8 + dn] = c[nb][0];
                Y[dr * 65 + nb * 8 + dn + 1] = c[nb][1];
                Y[(dr + 8) * 65 + nb * 8 + dn] = c[nb][2];
                Y[(dr + 8) * 65 + nb * 8 + dn + 1] = c[nb][3];
            }
        }
        __syncthreads();

        // ---- epilogue: gates + residual (agg reconstructed hi+lo) ----
#pragma unroll
        for (int half = 0; half < 2; half++) {
            int it = tid + half * 512;
            int a = it >> 6, o = it & 63;
            float y0 = Y[a * 65 + o] + b0s[o];
            float y1v[3], y2v[9];
#pragma unroll
            for (int p = 0; p < 3; p++) y1v[p] = Y[(16 + a * 3 + p) * 65 + o];
#pragma unroll
            for (int m = 0; m < 9; m++) y2v[m] = Y[(64 + a * 9 + m) * 65 + o];

            float ag[13];
            {
                int rows[13];
                rows[0] = a;
#pragma unroll
                for (int p = 0; p < 3; p++) rows[1 + p] = 16 + a * 3 + p;
#pragma unroll
                for (int m = 0; m < 9; m++) rows[4 + m] = 64 + a * 9 + m;
#pragma unroll
                for (int s = 0; s < 13; s++) {
                    uint32_t off = sw128((uint32_t)(rows[s] * 128 + o * 2));
                    ag[s] = __bfloat162float(*(__nv_bfloat16*)(B + OFF_A + off)) +
                            __bfloat162float(*(__nv_bfloat16*)(B + OFF_A + A_HALF + off));
                }
            }
            float z0 = y0 * sigf(aws[o] * y0);
            float n1 = y1v[0] * y1v[0] + y1v[1] * y1v[1] + y1v[2] * y1v[2];
            float g1 = sigf(aws[64 + o] * sqrtf(n1 + EPSF));
            float n2 = 0.f;
#pragma unroll
            for (int m = 0; m < 9; m++) n2 += y2v[m] * y2v[m];
            float g2 = sigf(aws[128 + o] * sqrtf(n2 + EPSF));
            size_t bo = (size_t)(nbase + a) * CDIM + o;
            out[bo] = z0 + ag[0];
#pragma unroll
            for (int p = 0; p < 3; p++) out1[bo * 3 + p] = y1v[p] * g1 + ag[1 + p];
#pragma unroll
            for (int m = 0; m < 9; m++) out2[bo * 9 + m] = y2v[m] * g2 + ag[4 + m];
        }
        __syncthreads();   // A / Y reused next tile
    }
}

extern "C" void kernel_launch(void* const* d_in, const int* in_sizes, int n_in,
                              void* d_out, int out_size) {
    const float* t0    = (const float*)d_in[0];
    const float* t1    = (const float*)d_in[1];
    const float* t2    = (const float*)d_in[2];
    const float* coord = (const float*)d_in[3];
    const int*   eidx  = (const int*)d_in[4];
    const float* rbf_w = (const float*)d_in[5];
    const float* w0    = (const float*)d_in[6];
    const float* b0    = (const float*)d_in[7];
    const float* w1    = (const float*)d_in[8];
    const float* w2    = (const float*)d_in[9];
    const float* aw    = (const float*)d_in[10];
    float* out = (float*)d_out;

    cudaFuncSetAttribute(k_si_mma, cudaFuncAttributeMaxDynamicSharedMemorySize, DYN_SZ);

    k_reset<<<(NATOMS + 255) / 256, 256>>>();
    k_compact<<<(NEDGES + 255) / 256, 256>>>(eidx, coord);
    k_zero_touched<<<2048, 64>>>();
    k_edge<<<888, 256>>>(eidx, coord, t0, t1, t2, rbf_w);
    k_si_mma<<<148, 512, DYN_SZ>>>(t0, t1, t2, w0, b0, w1, w2, aw, out);
}

// round 10
// speedup vs baseline: 1.0027x; 1.0027x over previous
#include <cuda_runtime.h>
#include <cuda_bf16.h>
#include <math.h>
#include <stdint.h>

#define NATOMS 20000
#define NEDGES 200000
#define CDIM 64
#define KDIM 20
#define RCUT 5.0f
#define NORMF 10.0f
#define EPSF 1e-12f
#define PI_F 3.14159265358979f
#define NC (NATOMS * CDIM)

// ---- dynamic smem layout (byte offsets from 1024-aligned base) ----
// W: 3 ways x {hi,lo} x (64 rows(o) x 128B(cc)) SW128   = 49152
// A: {hi,lo} x (128 rows x 128B) SW128                  = 32768
// Y: 104 rows x 65 floats                               = 27040
#define OFF_W    0
#define OFF_A    49152
#define A_HALF   16384
#define OFF_Y    81920
#define OFF_CTRL 109056     // b0s[64] @ +0, aws[192] @ +256
#define DYN_SZ   (OFF_CTRL + 1024 + 1024)

__device__ float g_scr[(size_t)13 * NC];
__device__ int g_active[NEDGES];
__device__ int g_flag[NATOMS];
__device__ int g_touched[NATOMS];
__device__ int g_count;
__device__ int g_ntouched;

__global__ void k_reset() {
    int idx = blockIdx.x * blockDim.x + threadIdx.x;
    if (idx < NATOMS) g_flag[idx] = 0;
    if (idx == 0) { g_count = 0; g_ntouched = 0; }
}

__global__ void k_compact(const int* __restrict__ eidx, const float* __restrict__ coord) {
    int e = blockIdx.x * blockDim.x + threadIdx.x;
    if (e >= NEDGES) return;
    int i = eidx[e];
    int j = eidx[NEDGES + e];
    float dx = coord[3 * j + 0] - coord[3 * i + 0];
    float dy = coord[3 * j + 1] - coord[3 * i + 1];
    float dz = coord[3 * j + 2] - coord[3 * i + 2];
    float d2 = dx * dx + dy * dy + dz * dz + EPSF;
    if (d2 < RCUT * RCUT) {     // fc == 0 exactly (fp32) beyond cutoff
        int p = atomicAdd(&g_count, 1);
        g_active[p] = e;
        if (atomicOr(&g_flag[i], 1) == 0) {
            int q = atomicAdd(&g_ntouched, 1);
            g_touched[q] = i;
        }
    }
}

__global__ void k_zero_touched() {
    const int nt = g_ntouched;
    for (int t = blockIdx.x; t < nt; t += gridDim.x) {
        size_t b = (size_t)g_touched[t] * CDIM + threadIdx.x;   // 64 threads
#pragma unroll
        for (int s = 0; s < 13; s++) g_scr[(size_t)s * NC + b] = 0.f;
    }
}

__global__ void k_edge(const int* __restrict__ eidx, const float* __restrict__ coord,
                       const float* __restrict__ t0, const float* __restrict__ t1,
                       const float* __restrict__ t2, const float* __restrict__ rbf_w) {
    __shared__ float rbf_sh[4][KDIM];
    const int tid = threadIdx.x;
    const int c = tid & 63;
    const int es = tid >> 6;
    const int count = g_count;

    for (int base = blockIdx.x * 4; base < count; base += gridDim.x * 4) {
        int ae = base + es;
        bool act = ae < count;
        int i = 0, j = 0;
        float ux = 0.f, uy = 0.f, uz = 0.f;
        if (act) {
            int e = g_active[ae];
            i = eidx[e];
            j = eidx[NEDGES + e];
            float dx = coord[3 * j + 0] - coord[3 * i + 0];
            float dy = coord[3 * j + 1] - coord[3 * i + 1];
            float dz = coord[3 * j + 2] - coord[3 * i + 2];
            float d2 = dx * dx + dy * dy + dz * dz + EPSF;
            float d = sqrtf(d2);
            float inv = 1.0f / d;
            ux = dx * inv; uy = dy * inv; uz = dz * inv;
            if (c < KDIM) {
                float x = fminf(d * (1.0f / RCUT), 1.0f);
                float fc = 0.5f * (cosf(PI_F * x) + 1.0f);
                float pref = sqrtf(2.0f / RCUT);
                rbf_sh[es][c] = pref * sinf((float)(c + 1) * PI_F * d * (1.0f / RCUT)) * inv * fc;
            }
        }
        __syncthreads();
        if (act) {
            float rbf[KDIM];
#pragma unroll
            for (int k = 0; k < KDIM; k++) rbf[k] = rbf_sh[es][k];

            float fn[11];
            for (int m = 0; m < 11; m++) {
                const float* w = rbf_w + (size_t)m * KDIM * CDIM + c;
                float acc = 0.f;
#pragma unroll
                for (int k = 0; k < KDIM; k++) acc += rbf[k] * __ldg(w + k * CDIM);
                fn[m] = acc;
            }

            size_t bj = (size_t)j * CDIM + c;
            float s0 = __ldg(t0 + bj);
            float va[3];
            va[0] = __ldg(t1 + bj * 3 + 0);
            va[1] = __ldg(t1 + bj * 3 + 1);
            va[2] = __ldg(t1 + bj * 3 + 2);
            float M[9];
#pragma unroll
            for (int m9 = 0; m9 < 9; m9++) M[m9] = __ldg(t2 + bj * 9 + m9);

            float u[3] = {ux, uy, uz};
            float d1 = va[0] * ux + va[1] * uy + va[2] * uz;
            float w3[3];
#pragma unroll
            for (int a = 0; a < 3; a++)
                w3[a] = M[a * 3 + 0] * ux + M[a * 3 + 1] * uy + M[a * 3 + 2] * uz;
            float q2 = w3[0] * ux + w3[1] * uy + w3[2] * uz;

            const float sc = 1.0f / NORMF;
            float o0 = (fn[0] * s0 + fn[4] * d1 + fn[9] * q2) * sc;
            float c1 = fn[1] * s0 + fn[6] * d1;
            float o1[3];
#pragma unroll
            for (int p = 0; p < 3; p++)
                o1[p] = (c1 * u[p] + fn[3] * va[p] + fn[8] * w3[p]) * sc;
            float o2[9];
#pragma unroll
            for (int a = 0; a < 3; a++) {
                float ga = fn[2] * s0 * u[a] + fn[5] * va[a] + fn[10] * w3[a];
#pragma unroll
                for (int b = 0; b < 3; b++)
                    o2[a * 3 + b] = (ga * u[b] + fn[7] * M[a * 3 + b]) * sc;
            }

            size_t bi = (size_t)i * CDIM + c;
            atomicAdd(&g_scr[bi], o0);
#pragma unroll
            for (int p = 0; p < 3; p++) atomicAdd(&g_scr[(size_t)(1 + p) * NC + bi], o1[p]);
#pragma unroll
            for (int m9 = 0; m9 < 9; m9++) atomicAdd(&g_scr[(size_t)(4 + m9) * NC + bi], o2[m9]);
        }
        __syncthreads();
    }
}

// ---- warp-mma helpers (base ISA, compiles for plain sm_103) ----
__device__ __forceinline__ uint32_t smem_u32(const void* p) {
    uint32_t a;
    asm("{ .reg .u64 t; cvta.to.shared.u64 t, %1; cvt.u32.u64 %0, t; }" : "=r"(a) : "l"(p));
    return a;
}
__device__ __forceinline__ uint32_t sw128(uint32_t o) { return o ^ ((o >> 3) & 0x70); }
__device__ __forceinline__ void ldsm4(uint32_t d[4], uint32_t addr) {
    asm volatile("ldmatrix.sync.aligned.m8n8.x4.shared.b16 {%0,%1,%2,%3}, [%4];"
                 : "=r"(d[0]), "=r"(d[1]), "=r"(d[2]), "=r"(d[3]) : "r"(addr));
}
__device__ __forceinline__ void ldsm2(uint32_t d[2], uint32_t addr) {
    asm volatile("ldmatrix.sync.aligned.m8n8.x2.shared.b16 {%0,%1}, [%2];"
                 : "=r"(d[0]), "=r"(d[1]) : "r"(addr));
}
__device__ __forceinline__ void mma_bf16(float c[4], const uint32_t a[4],
                                         uint32_t b0, uint32_t b1) {
    asm volatile("mma.sync.aligned.m16n8k16.row.col.f32.bf16.bf16.f32 "
                 "{%0,%1,%2,%3}, {%4,%5,%6,%7}, {%8,%9}, {%0,%1,%2,%3};"
                 : "+f"(c[0]), "+f"(c[1]), "+f"(c[2]), "+f"(c[3])
                 : "r"(a[0]), "r"(a[1]), "r"(a[2]), "r"(a[3]), "r"(b0), "r"(b1));
}
__device__ __forceinline__ float sigf(float x) { return 1.0f / (1.0f + __expf(-x)); }

// A-row validity map -> compact Y row (or -1).
// rows: way0 0-7, pad 8-15, way1 16-39, pad 40-47, way2 48-119, pad 120-127.
__device__ __forceinline__ int ymap(int gr) {
    if (gr < 8) return gr;
    if (gr < 16) return -1;
    if (gr < 40) return gr - 8;
    if (gr < 48) return -1;
    if (gr < 120) return gr - 16;
    return -1;
}

// Persistent split-bf16 mma.sync self-interaction, 8 atoms/tile, 256 threads,
// ~108KB smem -> 2 CTAs/SM so one CTA's gmem staging overlaps the other's mma.
// Warp w (<8) owns A rows [16w,16w+16): w0 way0, w1-2 way1, w3-7 way2
// (pad rows zeroed once, never written). D = Ah*Wh + Ah*Wl + Al*Wh (fp32 acc).
__global__ void __launch_bounds__(256, 2)
k_si_mma(const float* __restrict__ t0, const float* __restrict__ t1,
         const float* __restrict__ t2,
         const float* __restrict__ w0, const float* __restrict__ b0,
         const float* __restrict__ w1, const float* __restrict__ w2,
         const float* __restrict__ actw, float* __restrict__ out) {
    extern __shared__ char dsm[];
    uint32_t sb_raw = smem_u32(dsm);
    uint32_t base = (sb_raw + 1023u) & ~1023u;
    char* B = dsm + (base - sb_raw);
    float* Y = (float*)(B + OFF_Y);
    float* b0s = (float*)(B + OFF_CTRL);
    float* aws = (float*)(B + OFF_CTRL + 256);

    const int tid = threadIdx.x;
    const int w = tid >> 5, lane = tid & 31;

    // zero whole A (pads stay zero forever; valid rows rewritten each tile)
    { uint32_t* Az = (uint32_t*)(B + OFF_A);
      for (int i = tid; i < 32768 / 4; i += 256) Az[i] = 0u; }

    // ---- load W^T split hi/lo, SW128 (row = out channel o, col = cc) ----
    for (int idx = tid; idx < 3 * 64 * 64; idx += 256) {
        int way = idx >> 12, rem = idx & 4095;
        int o = rem >> 6, cc = rem & 63;
        const float* wsrc = (way == 0) ? w0 : ((way == 1) ? w1 : w2);
        float f = wsrc[cc * 64 + o];
        __nv_bfloat16 h = __float2bfloat16(f);
        __nv_bfloat16 l = __float2bfloat16(f - __bfloat162float(h));
        uint32_t off = sw128((uint32_t)(o * 128 + cc * 2));
        *(__nv_bfloat16*)(B + OFF_W + way * 16384 + off) = h;
        *(__nv_bfloat16*)(B + OFF_W + way * 16384 + 8192 + off) = l;
    }
    if (tid < 64) {
        b0s[tid] = b0[tid];
        aws[tid] = actw[tid];
        aws[64 + tid] = actw[64 + tid];
        aws[128 + tid] = actw[128 + tid];
    }
    __syncthreads();

    float* out1 = out + (size_t)NATOMS * CDIM;
    float* out2 = out + (size_t)NATOMS * CDIM * 4;

    for (int tile = blockIdx.x; tile < NATOMS / 8; tile += gridDim.x) {
        const int nbase = tile * 8;

        // ---- stage: agg fp32 = t + scr(touched), split into Ahi/Alo bf16 ----
        {
            int sc = tid & 63;
#pragma unroll
            for (int pass = 0; pass < 2; pass++) {
                int aa = (tid >> 6) + pass * 4;
                int n_a = nbase + aa;
                size_t gb = (size_t)n_a * CDIM + sc;
                float v[13];
                v[0] = t0[gb];
#pragma unroll
                for (int p = 0; p < 3; p++) v[1 + p] = t1[gb * 3 + p];
#pragma unroll
                for (int m = 0; m < 9; m++) v[4 + m] = t2[gb * 9 + m];
                if (g_flag[n_a]) {
#pragma unroll
                    for (int s = 0; s < 13; s++) v[s] += g_scr[(size_t)s * NC + gb];
                }
                int rows[13];
                rows[0] = aa;
#pragma unroll
                for (int p = 0; p < 3; p++) rows[1 + p] = 16 + aa * 3 + p;
#pragma unroll
                for (int m = 0; m < 9; m++) rows[4 + m] = 48 + aa * 9 + m;
#pragma unroll
                for (int s = 0; s < 13; s++) {
                    __nv_bfloat16 h = __float2bfloat16(v[s]);
                    __nv_bfloat16 l = __float2bfloat16(v[s] - __bfloat162float(h));
                    uint32_t off = sw128((uint32_t)(rows[s] * 128 + sc * 2));
                    *(__nv_bfloat16*)(B + OFF_A + off) = h;
                    *(__nv_bfloat16*)(B + OFF_A + A_HALF + off) = l;
                }
            }
        }
        __syncthreads();

        // ---- mma: warp w computes A rows [16w, 16w+16) ----
        {
            int way = (w == 0) ? 0 : ((w < 3) ? 1 : 2);
            uint32_t WhB = base + OFF_W + way * 16384;
            uint32_t WlB = WhB + 8192;
            uint32_t AhB = base + OFF_A, AlB = AhB + A_HALF;
            int rb = w * 16;
            int g = lane >> 3, lr = lane & 7;
            int arow = rb + ((g & 1) << 3) + lr;
            int acx = (g >> 1) << 4;
            uint32_t ah[4][4], al[4][4];
#pragma unroll
            for (int kc = 0; kc < 4; kc++) {
                uint32_t off = sw128((uint32_t)(arow * 128 + kc * 32 + acx));
                ldsm4(ah[kc], AhB + off);
                ldsm4(al[kc], AlB + off);
            }
            float c[8][4];
#pragma unroll
            for (int nb = 0; nb < 8; nb++)
#pragma unroll
                for (int q = 0; q < 4; q++) c[nb][q] = 0.f;

            int bl = lane & 15;
            int brow_l = bl & 7, bhalf = bl >> 3;
#pragma unroll
            for (int nb = 0; nb < 8; nb++) {
#pragma unroll
                for (int kc = 0; kc < 4; kc++) {
                    uint32_t boff = sw128((uint32_t)((nb * 8 + brow_l) * 128 + kc * 32 + bhalf * 16));
                    uint32_t bh[2], blo[2];
                    ldsm2(bh, WhB + boff);
                    ldsm2(blo, WlB + boff);
                    mma_bf16(c[nb], ah[kc], bh[0], bh[1]);
                    mma_bf16(c[nb], ah[kc], blo[0], blo[1]);
                    mma_bf16(c[nb], al[kc], bh[0], bh[1]);
                }
            }
            // D frag -> compact Y (skip pad rows)
            int dr = rb + (lane >> 2), dn = (lane & 3) * 2;
            int y0r = ymap(dr), y1r = ymap(dr + 8);
#pragma unroll
            for (int nb = 0; nb < 8; nb++) {
                if (y0r >= 0) {
                    Y[y0r * 65 + nb * 8 + dn] = c[nb][0];
                    Y[y0r * 65 + nb * 8 + dn + 1] = c[nb][1];
                }
                if (y1r >= 0) {
                    Y[y1r * 65 + nb * 8 + dn] = c[nb][2];
                    Y[y1r * 65 + nb * 8 + dn + 1] = c[nb][3];
                }
            }
        }
        __syncthreads();

        // ---- epilogue: gates + residual (agg reconstructed hi+lo) ----
#pragma unroll
        for (int half = 0; half < 2; half++) {
            int it = tid + half * 256;
            int a = it >> 6, o = it & 63;
            float y0 = Y[a * 65 + o] + b0s[o];
            float y1v[3], y2v[9];
#pragma unroll
            for (int p = 0; p < 3; p++) y1v[p] = Y[(8 + a * 3 + p) * 65 + o];
#pragma unroll
            for (int m = 0; m < 9; m++) y2v[m] = Y[(32 + a * 9 + m) * 65 + o];

            float ag[13];
            {
                int rows[13];
                rows[0] = a;
#pragma unroll
                for (int p = 0; p < 3; p++) rows[1 + p] = 16 + a * 3 + p;
#pragma unroll
                for (int m = 0; m < 9; m++) rows[4 + m] = 48 + a * 9 + m;
#pragma unroll
                for (int s = 0; s < 13; s++) {
                    uint32_t off = sw128((uint32_t)(rows[s] * 128 + o * 2));
                    ag[s] = __bfloat162float(*(__nv_bfloat16*)(B + OFF_A + off)) +
                            __bfloat162float(*(__nv_bfloat16*)(B + OFF_A + A_HALF + off));
                }
            }
            float z0 = y0 * sigf(aws[o] * y0);
            float n1 = y1v[0] * y1v[0] + y1v[1] * y1v[1] + y1v[2] * y1v[2];
            float g1 = sigf(aws[64 + o] * sqrtf(n1 + EPSF));
            float n2 = 0.f;
#pragma unroll
            for (int m = 0; m < 9; m++) n2 += y2v[m] * y2v[m];
            float g2 = sigf(aws[128 + o] * sqrtf(n2 + EPSF));
            size_t bo = (size_t)(nbase + a) * CDIM + o;
            out[bo] = z0 + ag[0];
#pragma unroll
            for (int p = 0; p < 3; p++) out1[bo * 3 + p] = y1v[p] * g1 + ag[1 + p];
#pragma unroll
            for (int m = 0; m < 9; m++) out2[bo * 9 + m] = y2v[m] * g2 + ag[4 + m];
        }
        __syncthreads();   // A / Y reused next tile
    }
}

extern "C" void kernel_launch(void* const* d_in, const int* in_sizes, int n_in,
                              void* d_out, int out_size) {
    const float* t0    = (const float*)d_in[0];
    const float* t1    = (const float*)d_in[1];
    const float* t2    = (const float*)d_in[2];
    const float* coord = (const float*)d_in[3];
    const int*   eidx  = (const int*)d_in[4];
    const float* rbf_w = (const float*)d_in[5];
    const float* w0    = (const float*)d_in[6];
    const float* b0    = (const float*)d_in[7];
    const float* w1    = (const float*)d_in[8];
    const float* w2    = (const float*)d_in[9];
    const float* aw    = (const float*)d_in[10];
    float* out = (float*)d_out;

    cudaFuncSetAttribute(k_si_mma, cudaFuncAttributeMaxDynamicSharedMemorySize, DYN_SZ);

    k_reset<<<(NATOMS + 255) / 256, 256>>>();
    k_compact<<<(NEDGES + 255) / 256, 256>>>(eidx, coord);
    k_zero_touched<<<2048, 64>>>();
    k_edge<<<888, 256>>>(eidx, coord, t0, t1, t2, rbf_w);
    k_si_mma<<<592, 256, DYN_SZ>>>(t0, t1, t2, w0, b0, w1, w2, aw, out);
}